// round 1
// baseline (speedup 1.0000x reference)
#include <cuda_runtime.h>

// SpatialWeightsEsDot: att[b,h,w,1,49] = softmax_off( window-masked 3x3-boxsum of
//   M_{dy,dx}[y,x] = sum_c phi[b,c,y,x]*phi[b,c,y+dy,x+dx] ), phi = w_phi @ u (1x1 conv).
// Shapes fixed: u [2,64,128,128] f32, w_phi [64,64] f32, out [2,128,128,1,49] f32.

#define HH 128
#define WW 128
#define CC 64
#define TILE 16
#define MG 18            // M grid per block = TILE + 2 (3x3 boxsum halo)
#define PG 24            // phi tile per block = TILE + 2 + 6 (window halo)
#define SPITCH 68        // floats per phi-tile position (64 + 4 pad); 272B = 17 float4 (16B aligned, 4-bank skew)
#define NOFF 49
#define S_PHI_FLOATS (PG * PG * SPITCH)      // 39168
#define S_M_FLOATS   (NOFF * MG * MG)        // 15876
#define SMEM_BYTES   ((S_PHI_FLOATS + S_M_FLOATS) * 4)  // 220176 B

// Scratch: phi in pixel-major layout [b][y][x][c] (c contiguous -> coalesced tile loads)
__device__ float g_phi[2 * HH * WW * CC];

// ---------------------------------------------------------------------------
// Kernel 1: phi[b,o,y,x] = sum_i w[o,i] * u[b,i,y,x]; stored pixel-major.
// One thread per pixel; u channel vector in regs; w broadcast from smem.
// ---------------------------------------------------------------------------
__global__ void __launch_bounds__(256, 1)
phi_kernel(const float* __restrict__ u, const float* __restrict__ w) {
    __shared__ float s_w[CC * CC];
    int tid = threadIdx.x;
    for (int i = tid; i < CC * CC; i += 256) s_w[i] = w[i];
    __syncthreads();

    int pix = blockIdx.x * 256 + tid;          // 0..32767 (b*16384 + p)
    int b   = pix >> 14;
    int p   = pix & 16383;

    const float* ub = u + b * CC * 16384 + p;
    float ur[CC];
#pragma unroll
    for (int i = 0; i < CC; i++) ur[i] = ub[i * 16384];

    float4* outp = (float4*)(g_phi + (size_t)pix * CC);
    const float4* w4 = (const float4*)s_w;

#pragma unroll 2
    for (int o = 0; o < CC; o += 4) {
        float a0 = 0.f, a1 = 0.f, a2 = 0.f, a3 = 0.f;
#pragma unroll
        for (int k = 0; k < CC / 4; k++) {
            float4 w0 = w4[(o + 0) * 16 + k];
            float4 w1 = w4[(o + 1) * 16 + k];
            float4 w2 = w4[(o + 2) * 16 + k];
            float4 w3 = w4[(o + 3) * 16 + k];
            float u0 = ur[4 * k + 0], u1 = ur[4 * k + 1];
            float u2 = ur[4 * k + 2], u3 = ur[4 * k + 3];
            a0 += w0.x * u0 + w0.y * u1 + w0.z * u2 + w0.w * u3;
            a1 += w1.x * u0 + w1.y * u1 + w1.z * u2 + w1.w * u3;
            a2 += w2.x * u0 + w2.y * u1 + w2.z * u2 + w2.w * u3;
            a3 += w3.x * u0 + w3.y * u1 + w3.z * u2 + w3.w * u3;
        }
        outp[o >> 2] = make_float4(a0, a1, a2, a3);
    }
}

// ---------------------------------------------------------------------------
// Kernel 2: per 16x16 pixel tile — load 24x24 phi halo into smem, compute all
// 49 M maps on the 18x18 M grid (center vec in regs, shifted vec from smem),
// then 3x3 boxsum + window mask + softmax + store. 2 barriers total.
// ---------------------------------------------------------------------------
__global__ void __launch_bounds__(384, 1)
attn_kernel(float* __restrict__ out) {
    extern __shared__ float smem[];
    float* s_phi = smem;
    float* s_M   = smem + S_PHI_FLOATS;

    int tid = threadIdx.x;
    int b   = blockIdx.z;
    int h0  = blockIdx.y * TILE;
    int w0  = blockIdx.x * TILE;

    // ---- Load phi halo tile (24x24 positions x 64ch), zero outside image ----
    for (int idx = tid; idx < PG * PG * 16; idx += 384) {
        int pos = idx >> 4;
        int c4  = idx & 15;
        int py  = pos / PG;
        int px  = pos - py * PG;
        int y = h0 - 4 + py;
        int x = w0 - 4 + px;
        float4 v = make_float4(0.f, 0.f, 0.f, 0.f);
        if ((unsigned)y < HH && (unsigned)x < WW)
            v = *(const float4*)(g_phi + ((((b << 7) + y) << 7) + x) * CC + (c4 << 2));
        *(float4*)(s_phi + pos * SPITCH + (c4 << 2)) = v;
    }
    __syncthreads();

    // ---- M maps: thread tid<324 owns M-position (my,mx); center vec in regs ----
    if (tid < MG * MG) {
        int my = tid / MG;
        int mx = tid - my * MG;
        const float4* cb = (const float4*)(s_phi + ((my + 3) * PG + (mx + 3)) * SPITCH);
        float4 c[16];
#pragma unroll
        for (int k = 0; k < 16; k++) c[k] = cb[k];

#pragma unroll 1
        for (int off = 0; off < NOFF; off++) {
            int dy = off / 7 - 3;
            int dx = off - (off / 7) * 7 - 3;
            const float4* sb = cb + (dy * PG + dx) * (SPITCH / 4);
            float a0 = 0.f, a1 = 0.f, a2 = 0.f, a3 = 0.f;
#pragma unroll
            for (int k = 0; k < 16; k += 4) {
                float4 v0 = sb[k + 0];
                float4 v1 = sb[k + 1];
                float4 v2 = sb[k + 2];
                float4 v3 = sb[k + 3];
                a0 += c[k + 0].x * v0.x + c[k + 0].y * v0.y + c[k + 0].z * v0.z + c[k + 0].w * v0.w;
                a1 += c[k + 1].x * v1.x + c[k + 1].y * v1.y + c[k + 1].z * v1.z + c[k + 1].w * v1.w;
                a2 += c[k + 2].x * v2.x + c[k + 2].y * v2.y + c[k + 2].z * v2.z + c[k + 2].w * v2.w;
                a3 += c[k + 3].x * v3.x + c[k + 3].y * v3.y + c[k + 3].z * v3.z + c[k + 3].w * v3.w;
            }
            s_M[off * (MG * MG) + tid] = (a0 + a1) + (a2 + a3);
        }
    }
    __syncthreads();

    // ---- Boxsum + mask + softmax + store: thread tid<256 owns pixel (py,px) ----
    if (tid < TILE * TILE) {
        int py = tid >> 4;
        int px = tid & 15;
        int h = h0 + py;
        int w = w0 + px;

        float att[NOFF];
#pragma unroll 1
        for (int off = 0; off < NOFF; off++) {
            int dy = off / 7 - 3;
            int dx = off - (off / 7) * 7 - 3;
            const float* m = s_M + off * (MG * MG) + py * MG + px;
            float s = m[0] + m[1] + m[2]
                    + m[MG] + m[MG + 1] + m[MG + 2]
                    + m[2 * MG] + m[2 * MG + 1] + m[2 * MG + 2];
            bool valid = ((unsigned)(h + dy) < HH) && ((unsigned)(w + dx) < WW);
            att[off] = valid ? s : 0.0f;
        }

        float mx = att[0];
#pragma unroll
        for (int o = 1; o < NOFF; o++) mx = fmaxf(mx, att[o]);
        float sum = 0.f;
#pragma unroll
        for (int o = 0; o < NOFF; o++) { float e = __expf(att[o] - mx); att[o] = e; sum += e; }
        float inv = 1.0f / sum;

        float* op = out + (((size_t)(b * HH + h)) * WW + w) * NOFF;
#pragma unroll
        for (int o = 0; o < NOFF; o++) op[o] = att[o] * inv;
    }
}

extern "C" void kernel_launch(void* const* d_in, const int* in_sizes, int n_in,
                              void* d_out, int out_size) {
    const float* u = (const float*)d_in[0];    // [2,64,128,128]
    const float* w = (const float*)d_in[1];    // [64,64]
    float* out = (float*)d_out;                // [2,128,128,1,49]

    cudaFuncSetAttribute(attn_kernel, cudaFuncAttributeMaxDynamicSharedMemorySize, SMEM_BYTES);

    phi_kernel<<<(2 * HH * WW) / 256, 256>>>(u, w);
    dim3 grid(WW / TILE, HH / TILE, 2);
    attn_kernel<<<grid, 384, SMEM_BYTES>>>(out);
}